// round 9
// baseline (speedup 1.0000x reference)
#include <cuda_runtime.h>
#include <cuda_pipeline.h>

#define G  7
#define GG 49            // G*G
#define CH 1470          // 30*GG
#define NB 2             // batches staged per block
#define THREADS 256

__device__ float        g_accum = 0.0f;
__device__ unsigned int g_count = 0;

__device__ __forceinline__ float warp_sum(float v) {
    #pragma unroll
    for (int o = 16; o > 0; o >>= 1) v += __shfl_down_sync(0xffffffffu, v, o);
    return v;
}

__global__ __launch_bounds__(THREADS) void yolo_loss_kernel(
    const float* __restrict__ pred,
    const float* __restrict__ lab,
    float* __restrict__ out,
    int B, float invB)
{
    __shared__ float s_pred[NB * CH];   // 11760 B
    __shared__ float s_lab [NB * CH];   // 11760 B
    __shared__ float warp_sums[8];

    const int bg = blockIdx.x;
    const long long base = (long long)bg * NB * CH;
    const int nb = min(NB, B - bg * NB);
    const int tid = threadIdx.x;

    if (nb == NB) {
        // fast path: stream 2*2940 floats as float4 via cp.async (L1-bypass)
        const float4* gp = (const float4*)(pred + base);
        const float4* gl = (const float4*)(lab  + base);
        float4* sp = (float4*)s_pred;
        float4* sl = (float4*)s_lab;
        constexpr int N4 = NB * CH / 4;   // 735
        #pragma unroll
        for (int i = tid; i < N4; i += THREADS) {
            __pipeline_memcpy_async(&sp[i], &gp[i], 16);
            __pipeline_memcpy_async(&sl[i], &gl[i], 16);
        }
    } else {
        // tail path: scalar copies (only if B % NB != 0)
        for (int i = tid; i < nb * CH; i += THREADS) {
            s_pred[i] = pred[base + i];
            s_lab[i]  = lab [base + i];
        }
    }
    __pipeline_commit();
    __pipeline_wait_prior(0);
    __syncthreads();

    float loss = 0.0f;
    const int bl   = tid / GG;        // local batch index (valid for tid < NB*GG)
    const int cell = tid - bl * GG;   // 0..48
    if (tid < NB * GG && bl < nb) {
        const int m = cell / G;       // dim-2 index, pairs with x
        const int n = cell % G;       // dim-3 index, pairs with y

        const float* p = s_pred + bl * CH + cell;
        const float* l = s_lab  + bl * CH + cell;

        float pv[10];
        #pragma unroll
        for (int c = 0; c < 10; c++) pv[c] = p[c * GG];
        float lv[9];
        #pragma unroll
        for (int c = 0; c < 9; c++) lv[c] = l[c * GG];

        const float mf = (float)m;
        const float nf = (float)n;
        const float invG = 1.0f / (float)G;

        // --- boxes in xyxy ---
        float cx1 = (pv[0] + mf) * invG, cy1 = (pv[1] + nf) * invG;
        float x1a = cx1 - pv[2] * 0.5f, y1a = cy1 - pv[3] * 0.5f;
        float x2a = cx1 + pv[2] * 0.5f, y2a = cy1 + pv[3] * 0.5f;
        float cx2 = (pv[5] + mf) * invG, cy2 = (pv[6] + nf) * invG;
        float x1b = cx2 - pv[7] * 0.5f, y1b = cy2 - pv[8] * 0.5f;
        float x2b = cx2 + pv[7] * 0.5f, y2b = cy2 + pv[8] * 0.5f;
        float cxg = (lv[0] + mf) * invG, cyg = (lv[1] + nf) * invG;
        float x1g = cxg - lv[2] * 0.5f, y1g = cyg - lv[3] * 0.5f;
        float x2g = cxg + lv[2] * 0.5f, y2g = cyg + lv[3] * 0.5f;

        // --- iou(box1, boxg) ---
        float iw1 = fmaxf(fminf(x2a, x2g) - fmaxf(x1a, x1g), 0.0f);
        float ih1 = fmaxf(fminf(y2a, y2g) - fmaxf(y1a, y1g), 0.0f);
        float inter1 = iw1 * ih1;
        float area_a = (x2a - x1a) * (y2a - y1a);
        float area_g = (x2g - x1g) * (y2g - y1g);
        float iou1 = (inter1 > 0.0f) ? inter1 / (area_a + area_g - inter1) : 0.0f;

        // --- iou(box2, boxg) ---
        float iw2 = fmaxf(fminf(x2b, x2g) - fmaxf(x1b, x1g), 0.0f);
        float ih2 = fmaxf(fminf(y2b, y2g) - fmaxf(y1b, y1g), 0.0f);
        float inter2 = iw2 * ih2;
        float area_b = (x2b - x1b) * (y2b - y1b);
        float iou2 = (inter2 > 0.0f) ? inter2 / (area_b + area_g - inter2) : 0.0f;

        bool resp1 = (iou1 >= iou2);

        // --- coord losses ---
        float d0 = pv[0] - lv[0], d1 = pv[1] - lv[1];
        float s2 = sqrtf(pv[2]) - sqrtf(lv[2]);
        float s3 = sqrtf(pv[3]) - sqrtf(lv[3]);
        float coor1 = 5.0f * (d0 * d0 + d1 * d1 + s2 * s2 + s3 * s3);

        float d5 = pv[5] - lv[5], d6 = pv[6] - lv[6];
        float s7 = sqrtf(pv[7]) - sqrtf(lv[7]);
        float s8 = sqrtf(pv[8]) - sqrtf(lv[8]);
        float coor2 = 5.0f * (d5 * d5 + d6 * d6 + s7 * s7 + s8 * s8);

        float e1 = pv[4] - iou1;
        float e2 = pv[9] - iou2;
        float loss_b1 = coor1 + e1 * e1 + 0.5f * e2 * e2;
        float loss_b2 = coor2 + e2 * e2 + 0.5f * e1 * e1;

        // --- class loss (channels 10..29) ---
        float cls = 0.0f;
        #pragma unroll
        for (int c = 10; c < 30; c++) {
            float d = p[c * GG] - l[c * GG];
            cls = fmaf(d, d, cls);
        }

        float obj_loss   = (resp1 ? loss_b1 : loss_b2) + cls;
        float noobj_loss = 0.5f * (pv[4] * pv[4] + pv[9] * pv[9]);

        loss = (lv[4] == 1.0f) ? obj_loss : noobj_loss;
    }

    // --- block reduction ---
    float v = warp_sum(loss);
    int lane = tid & 31;
    int wid  = tid >> 5;
    if (lane == 0) warp_sums[wid] = v;
    __syncthreads();
    if (wid == 0) {
        float bv = (lane < (THREADS >> 5)) ? warp_sums[lane] : 0.0f;
        bv = warp_sum(bv);
        if (lane == 0) {
            atomicAdd(&g_accum, bv);
            __threadfence();
            unsigned int old = atomicInc(&g_count, gridDim.x - 1);
            if (old == gridDim.x - 1) {
                float tot = atomicExch(&g_accum, 0.0f);
                out[0] = tot * invB;
            }
        }
    }
}

extern "C" void kernel_launch(void* const* d_in, const int* in_sizes, int n_in,
                              void* d_out, int out_size) {
    const float* pred = (const float*)d_in[0];
    const float* lab  = (const float*)d_in[1];
    float* out = (float*)d_out;

    int B = in_sizes[0] / CH;   // 32768
    int blocks = (B + NB - 1) / NB;

    yolo_loss_kernel<<<blocks, THREADS>>>(pred, lab, out, B, 1.0f / (float)B);
}

// round 10
// speedup vs baseline: 1.1895x; 1.1895x over previous
#include <cuda_runtime.h>

#define G  7
#define GG 49            // G*G
#define CH 1470          // 30*GG
#define NPAIR 25         // cell pairs per batch (last pair is singleton)
#define THREADS 128

__device__ float        g_accum = 0.0f;
__device__ unsigned int g_count = 0;

__device__ __forceinline__ float warp_sum(float v) {
    #pragma unroll
    for (int o = 16; o > 0; o >>= 1) v += __shfl_down_sync(0xffffffffu, v, o);
    return v;
}

__global__ __launch_bounds__(THREADS) void yolo_loss_kernel(
    const float* __restrict__ pred,
    const float* __restrict__ lab,
    float* __restrict__ out,
    int B, float invB)
{
    const long long total = (long long)B * NPAIR;
    long long idx = (long long)blockIdx.x * THREADS + threadIdx.x;

    float loss = 0.0f;
    if (idx < total) {
        const int b  = (int)(idx / NPAIR);
        const int cp = (int)(idx % NPAIR);

        const int cell0 = 2 * cp;
        const int cell1_raw = 2 * cp + 1;
        const bool v1 = (cell1_raw < GG);
        const int cell1 = v1 ? cell1_raw : (GG - 1);   // clamp; masked later

        const float* pb = pred + (long long)b * CH;
        const float* lb = lab  + (long long)b * CH;

        // ---- front-batched loads for BOTH cells (independent) ----
        float pv[2][10];
        float lv[2][9];
        #pragma unroll
        for (int c = 0; c < 10; c++) {
            pv[0][c] = pb[c * GG + cell0];
            pv[1][c] = pb[c * GG + cell1];
        }
        #pragma unroll
        for (int c = 0; c < 9; c++) {
            lv[0][c] = lb[c * GG + cell0];
            lv[1][c] = lb[c * GG + cell1];
        }
        float cls[2] = {0.0f, 0.0f};
        #pragma unroll
        for (int c = 10; c < 30; c++) {
            float p0 = pb[c * GG + cell0], l0 = lb[c * GG + cell0];
            float p1 = pb[c * GG + cell1], l1 = lb[c * GG + cell1];
            float d0 = p0 - l0, d1 = p1 - l1;
            cls[0] = fmaf(d0, d0, cls[0]);
            cls[1] = fmaf(d1, d1, cls[1]);
        }

        const float invG = 1.0f / (float)G;
        const int cells[2] = {cell0, cell1};
        const float mask[2] = {1.0f, v1 ? 1.0f : 0.0f};

        #pragma unroll
        for (int k = 0; k < 2; k++) {
            const int cell = cells[k];
            const float mf = (float)(cell / G);   // dim-2 index, pairs with x
            const float nf = (float)(cell % G);   // dim-3 index, pairs with y
            const float* PV = pv[k];
            const float* LV = lv[k];

            // --- boxes in xyxy ---
            float cx1 = (PV[0] + mf) * invG, cy1 = (PV[1] + nf) * invG;
            float x1a = cx1 - PV[2] * 0.5f, y1a = cy1 - PV[3] * 0.5f;
            float x2a = cx1 + PV[2] * 0.5f, y2a = cy1 + PV[3] * 0.5f;
            float cx2 = (PV[5] + mf) * invG, cy2 = (PV[6] + nf) * invG;
            float x1b = cx2 - PV[7] * 0.5f, y1b = cy2 - PV[8] * 0.5f;
            float x2b = cx2 + PV[7] * 0.5f, y2b = cy2 + PV[8] * 0.5f;
            float cxg = (LV[0] + mf) * invG, cyg = (LV[1] + nf) * invG;
            float x1g = cxg - LV[2] * 0.5f, y1g = cyg - LV[3] * 0.5f;
            float x2g = cxg + LV[2] * 0.5f, y2g = cyg + LV[3] * 0.5f;

            // --- iou(box1, boxg) ---
            float iw1 = fmaxf(fminf(x2a, x2g) - fmaxf(x1a, x1g), 0.0f);
            float ih1 = fmaxf(fminf(y2a, y2g) - fmaxf(y1a, y1g), 0.0f);
            float inter1 = iw1 * ih1;
            float area_a = (x2a - x1a) * (y2a - y1a);
            float area_g = (x2g - x1g) * (y2g - y1g);
            float iou1 = (inter1 > 0.0f) ? inter1 / (area_a + area_g - inter1) : 0.0f;

            // --- iou(box2, boxg) ---
            float iw2 = fmaxf(fminf(x2b, x2g) - fmaxf(x1b, x1g), 0.0f);
            float ih2 = fmaxf(fminf(y2b, y2g) - fmaxf(y1b, y1g), 0.0f);
            float inter2 = iw2 * ih2;
            float area_b = (x2b - x1b) * (y2b - y1b);
            float iou2 = (inter2 > 0.0f) ? inter2 / (area_b + area_g - inter2) : 0.0f;

            bool resp1 = (iou1 >= iou2);

            // --- coord losses ---
            float d0 = PV[0] - LV[0], d1 = PV[1] - LV[1];
            float s2 = sqrtf(PV[2]) - sqrtf(LV[2]);
            float s3 = sqrtf(PV[3]) - sqrtf(LV[3]);
            float coor1 = 5.0f * (d0 * d0 + d1 * d1 + s2 * s2 + s3 * s3);

            float d5 = PV[5] - LV[5], d6 = PV[6] - LV[6];
            float s7 = sqrtf(PV[7]) - sqrtf(LV[7]);
            float s8 = sqrtf(PV[8]) - sqrtf(LV[8]);
            float coor2 = 5.0f * (d5 * d5 + d6 * d6 + s7 * s7 + s8 * s8);

            float e1 = PV[4] - iou1;
            float e2 = PV[9] - iou2;
            float loss_b1 = coor1 + e1 * e1 + 0.5f * e2 * e2;
            float loss_b2 = coor2 + e2 * e2 + 0.5f * e1 * e1;

            float obj_loss   = (resp1 ? loss_b1 : loss_b2) + cls[k];
            float noobj_loss = 0.5f * (PV[4] * PV[4] + PV[9] * PV[9]);

            loss += mask[k] * ((LV[4] == 1.0f) ? obj_loss : noobj_loss);
        }
    }

    // --- block reduction (128 threads = 4 warps) ---
    __shared__ float warp_sums[4];
    float v = warp_sum(loss);
    int lane = threadIdx.x & 31;
    int wid  = threadIdx.x >> 5;
    if (lane == 0) warp_sums[wid] = v;
    __syncthreads();
    if (wid == 0) {
        float bv = (lane < (THREADS >> 5)) ? warp_sums[lane] : 0.0f;
        bv = warp_sum(bv);
        if (lane == 0) {
            atomicAdd(&g_accum, bv);
            __threadfence();
            unsigned int old = atomicInc(&g_count, gridDim.x - 1);
            if (old == gridDim.x - 1) {
                float tot = atomicExch(&g_accum, 0.0f);
                out[0] = tot * invB;
            }
        }
    }
}

extern "C" void kernel_launch(void* const* d_in, const int* in_sizes, int n_in,
                              void* d_out, int out_size) {
    const float* pred = (const float*)d_in[0];
    const float* lab  = (const float*)d_in[1];
    float* out = (float*)d_out;

    int B = in_sizes[0] / CH;   // 32768
    long long total = (long long)B * NPAIR;
    int blocks = (int)((total + THREADS - 1) / THREADS);

    yolo_loss_kernel<<<blocks, THREADS>>>(pred, lab, out, B, 1.0f / (float)B);
}